// round 1
// baseline (speedup 1.0000x reference)
#include <cuda_runtime.h>
#include <cuda_bf16.h>
#include <cstdint>

#define N_NODES 100000
#define DIM 128

// Scratch (allocation-free rule: __device__ globals)
__device__ float g_support[(size_t)N_NODES * DIM];
__device__ float g_agg[(size_t)N_NODES * DIM];
__device__ float g_trans[(size_t)N_NODES * DIM];
__device__ float g_gate[(size_t)N_NODES * DIM];

// ---------------------------------------------------------------------------
// Kernel 1: fused triple GEMM  C = x @ W  (W in {w1,w2,w3} by blockIdx.y)
// 128x128 block tile, BK=16, 256 threads, 8x8 per-thread microtile.
// Epilogue fuses bias / epsilon-scale / sigmoid and writes scratch arrays.
// ---------------------------------------------------------------------------
#define BM 128
#define BN 128
#define BK 16

__global__ __launch_bounds__(256, 2) void gemm3_kernel(
    const float* __restrict__ x,
    const float* __restrict__ w1, const float* __restrict__ w2,
    const float* __restrict__ w3,
    const float* __restrict__ b1, const float* __restrict__ b2,
    const float* __restrict__ b3,
    const float* __restrict__ eps, int M)
{
    __shared__ float As[BK][BM + 4];   // transposed x tile, padded
    __shared__ float Bs[BK][BN];       // W tile (k-major rows)

    const int mode = blockIdx.y;
    const float* __restrict__ W = (mode == 0) ? w1 : ((mode == 1) ? w2 : w3);

    const int m0  = blockIdx.x * BM;
    const int tid = threadIdx.x;
    const int tx  = tid & 15;   // 16 cols of threads
    const int ty  = tid >> 4;   // 16 rows of threads

    float acc[8][8];
#pragma unroll
    for (int i = 0; i < 8; i++)
#pragma unroll
        for (int j = 0; j < 8; j++) acc[i][j] = 0.f;

#pragma unroll
    for (int k0 = 0; k0 < DIM; k0 += BK) {
        // Load A tile: 128 rows x 16 k, 512 float4s, 2 per thread (transpose into As)
#pragma unroll
        for (int l = 0; l < 2; l++) {
            int idx = tid + l * 256;          // 0..511
            int r   = idx >> 2;               // row-in-tile 0..127
            int kc  = (idx & 3) << 2;         // k-chunk 0,4,8,12
            int row = m0 + r;
            float4 v = make_float4(0.f, 0.f, 0.f, 0.f);
            if (row < M)
                v = *(const float4*)(x + (size_t)row * DIM + k0 + kc);
            As[kc + 0][r] = v.x;
            As[kc + 1][r] = v.y;
            As[kc + 2][r] = v.z;
            As[kc + 3][r] = v.w;
        }
        // Load B tile: 16 k x 128 n, 512 float4s
#pragma unroll
        for (int l = 0; l < 2; l++) {
            int idx = tid + l * 256;
            int r   = idx >> 5;               // k 0..15
            int c   = (idx & 31) << 2;        // n 0..124
            *(float4*)(&Bs[r][c]) = *(const float4*)(W + (size_t)(k0 + r) * DIM + c);
        }
        __syncthreads();

#pragma unroll
        for (int kk = 0; kk < BK; kk++) {
            float a[8], b[8];
            *(float4*)(a)     = *(const float4*)(&As[kk][ty * 8]);
            *(float4*)(a + 4) = *(const float4*)(&As[kk][ty * 8 + 4]);
            *(float4*)(b)     = *(const float4*)(&Bs[kk][tx * 8]);
            *(float4*)(b + 4) = *(const float4*)(&Bs[kk][tx * 8 + 4]);
#pragma unroll
            for (int i = 0; i < 8; i++)
#pragma unroll
                for (int j = 0; j < 8; j++)
                    acc[i][j] = fmaf(a[i], b[j], acc[i][j]);
        }
        __syncthreads();
    }

    // ---- fused epilogue ----
    const int cbase = tx * 8;
    if (mode == 0) {
        const float e = *eps;
        float bb[8];
#pragma unroll
        for (int j = 0; j < 8; j++) bb[j] = b1[cbase + j];
#pragma unroll
        for (int i = 0; i < 8; i++) {
            int row = m0 + ty * 8 + i;
            if (row >= M) break;
            size_t base = (size_t)row * DIM + cbase;
            float4 s0 = make_float4(acc[i][0], acc[i][1], acc[i][2], acc[i][3]);
            float4 s1 = make_float4(acc[i][4], acc[i][5], acc[i][6], acc[i][7]);
            *(float4*)(g_support + base)     = s0;
            *(float4*)(g_support + base + 4) = s1;
            float4 a0 = make_float4(fmaf(e, s0.x, bb[0]), fmaf(e, s0.y, bb[1]),
                                    fmaf(e, s0.z, bb[2]), fmaf(e, s0.w, bb[3]));
            float4 a1 = make_float4(fmaf(e, s1.x, bb[4]), fmaf(e, s1.y, bb[5]),
                                    fmaf(e, s1.z, bb[6]), fmaf(e, s1.w, bb[7]));
            *(float4*)(g_agg + base)     = a0;
            *(float4*)(g_agg + base + 4) = a1;
        }
    } else if (mode == 1) {
        float bb[8];
#pragma unroll
        for (int j = 0; j < 8; j++) bb[j] = b2[cbase + j];
#pragma unroll
        for (int i = 0; i < 8; i++) {
            int row = m0 + ty * 8 + i;
            if (row >= M) break;
            size_t base = (size_t)row * DIM + cbase;
            float4 t0 = make_float4(acc[i][0] + bb[0], acc[i][1] + bb[1],
                                    acc[i][2] + bb[2], acc[i][3] + bb[3]);
            float4 t1 = make_float4(acc[i][4] + bb[4], acc[i][5] + bb[5],
                                    acc[i][6] + bb[6], acc[i][7] + bb[7]);
            *(float4*)(g_trans + base)     = t0;
            *(float4*)(g_trans + base + 4) = t1;
        }
    } else {
        float bb[8];
#pragma unroll
        for (int j = 0; j < 8; j++) bb[j] = b3[cbase + j];
#pragma unroll
        for (int i = 0; i < 8; i++) {
            int row = m0 + ty * 8 + i;
            if (row >= M) break;
            size_t base = (size_t)row * DIM + cbase;
            float g[8];
#pragma unroll
            for (int j = 0; j < 8; j++) {
                float t = acc[i][j] + bb[j];
                g[j] = 1.f / (1.f + __expf(-t));
            }
            *(float4*)(g_gate + base)     = make_float4(g[0], g[1], g[2], g[3]);
            *(float4*)(g_gate + base + 4) = make_float4(g[4], g[5], g[6], g[7]);
        }
    }
}

// ---------------------------------------------------------------------------
// Kernel 2: edge scatter. One warp per edge; lane handles 4 contiguous cols.
// Vectorized 16B reduction (red.global.add.v4.f32, sm_90+) to cut LSU issue 4x.
// ---------------------------------------------------------------------------
__global__ __launch_bounds__(256) void scatter_kernel(
    const int* __restrict__ esrc, const int* __restrict__ edst,
    const float* __restrict__ ew, int E)
{
    int gw   = (int)((blockIdx.x * blockDim.x + threadIdx.x) >> 5);
    int lane = threadIdx.x & 31;
    if (gw >= E) return;

    int   s  = __ldg(esrc + gw);
    int   d  = __ldg(edst + gw);
    float we = __ldg(ew + gw);

    float4 v = *((const float4*)(g_support + (size_t)s * DIM) + lane);
    v.x *= we; v.y *= we; v.z *= we; v.w *= we;

    float* p = g_agg + (size_t)d * DIM + lane * 4;
    asm volatile("red.global.add.v4.f32 [%0], {%1, %2, %3, %4};"
                 :: "l"(p), "f"(v.x), "f"(v.y), "f"(v.z), "f"(v.w)
                 : "memory");
}

// ---------------------------------------------------------------------------
// Kernel 3: final elementwise  out = trans + gate * (relu(agg) - trans)
// ---------------------------------------------------------------------------
__global__ __launch_bounds__(256) void final_kernel(float* __restrict__ out, int n4)
{
    int i = blockIdx.x * blockDim.x + threadIdx.x;
    if (i >= n4) return;
    float4 a = ((const float4*)g_agg)[i];
    float4 t = ((const float4*)g_trans)[i];
    float4 g = ((const float4*)g_gate)[i];
    float4 o;
    o.x = t.x + g.x * (fmaxf(a.x, 0.f) - t.x);
    o.y = t.y + g.y * (fmaxf(a.y, 0.f) - t.y);
    o.z = t.z + g.z * (fmaxf(a.z, 0.f) - t.z);
    o.w = t.w + g.w * (fmaxf(a.w, 0.f) - t.w);
    ((float4*)out)[i] = o;
}

// ---------------------------------------------------------------------------
extern "C" void kernel_launch(void* const* d_in, const int* in_sizes, int n_in,
                              void* d_out, int out_size)
{
    const float* x    = (const float*)d_in[0];
    const int*   esrc = (const int*)d_in[1];
    const int*   edst = (const int*)d_in[2];
    const float* ew   = (const float*)d_in[3];
    const float* w1   = (const float*)d_in[4];
    const float* w2   = (const float*)d_in[5];
    const float* w3   = (const float*)d_in[6];
    const float* b1   = (const float*)d_in[7];
    const float* b2   = (const float*)d_in[8];
    const float* b3   = (const float*)d_in[9];
    const float* eps  = (const float*)d_in[10];

    const int M = in_sizes[0] / DIM;   // 100000
    const int E = in_sizes[1];         // 1600000

    dim3 gg((M + BM - 1) / BM, 3);
    gemm3_kernel<<<gg, 256>>>(x, w1, w2, w3, b1, b2, b3, eps, M);

    long long total_threads = (long long)E * 32;
    int blocks = (int)((total_threads + 255) / 256);
    scatter_kernel<<<blocks, 256>>>(esrc, edst, ew, E);

    int n4 = M * DIM / 4;
    final_kernel<<<(n4 + 255) / 256, 256>>>((float*)d_out, n4);
}

// round 2
// speedup vs baseline: 1.1565x; 1.1565x over previous
#include <cuda_runtime.h>
#include <cuda_bf16.h>
#include <cstdint>

#define N_NODES 100000
#define N_EDGES_MAX 1600000
#define DIM 128

// ---------------- scratch (allocation-free rule: __device__ globals) -------
__device__ float g_support[(size_t)N_NODES * DIM];
__device__ float g_trans[(size_t)N_NODES * DIM];
__device__ float g_gate[(size_t)N_NODES * DIM];

__device__ __nv_bfloat16 g_xhi[(size_t)N_NODES * DIM];
__device__ __nv_bfloat16 g_xlo[(size_t)N_NODES * DIM];
__device__ __nv_bfloat16 g_wh[3 * DIM * DIM];
__device__ __nv_bfloat16 g_wl[3 * DIM * DIM];

__device__ int  g_cnt[N_NODES];
__device__ int  g_off[N_NODES + 1];
__device__ int  g_cur[N_NODES];
__device__ int2 g_csr[N_EDGES_MAX];   // {src, float_bits(weight)} bucketed by dst

// ---------------------------------------------------------------------------
// helpers
// ---------------------------------------------------------------------------
__device__ __forceinline__ uint32_t smem_u32(const void* p) {
    return (uint32_t)__cvta_generic_to_shared(p);
}
__device__ __forceinline__ void ldsm_x4(uint32_t& r0, uint32_t& r1, uint32_t& r2,
                                        uint32_t& r3, uint32_t addr) {
    asm volatile("ldmatrix.sync.aligned.m8n8.x4.shared.b16 {%0,%1,%2,%3}, [%4];"
                 : "=r"(r0), "=r"(r1), "=r"(r2), "=r"(r3) : "r"(addr));
}
__device__ __forceinline__ void ldsm_x4_t(uint32_t& r0, uint32_t& r1, uint32_t& r2,
                                          uint32_t& r3, uint32_t addr) {
    asm volatile("ldmatrix.sync.aligned.m8n8.x4.trans.shared.b16 {%0,%1,%2,%3}, [%4];"
                 : "=r"(r0), "=r"(r1), "=r"(r2), "=r"(r3) : "r"(addr));
}
__device__ __forceinline__ void mma_bf16(float* c, uint32_t a0, uint32_t a1,
                                         uint32_t a2, uint32_t a3,
                                         uint32_t b0, uint32_t b1) {
    asm volatile(
        "mma.sync.aligned.m16n8k16.row.col.f32.bf16.bf16.f32 "
        "{%0,%1,%2,%3}, {%4,%5,%6,%7}, {%8,%9}, {%0,%1,%2,%3};"
        : "+f"(c[0]), "+f"(c[1]), "+f"(c[2]), "+f"(c[3])
        : "r"(a0), "r"(a1), "r"(a2), "r"(a3), "r"(b0), "r"(b1));
}

// ---------------------------------------------------------------------------
// prep: split w1/w2/w3 into bf16 hi/lo, zero the dst-degree histogram
// ---------------------------------------------------------------------------
__global__ void prep_kernel(const float* __restrict__ w1, const float* __restrict__ w2,
                            const float* __restrict__ w3) {
    int i = blockIdx.x * blockDim.x + threadIdx.x;
    if (i < 3 * DIM * DIM) {
        int mode = i / (DIM * DIM);
        int off  = i - mode * DIM * DIM;
        float v = (mode == 0) ? w1[off] : ((mode == 1) ? w2[off] : w3[off]);
        __nv_bfloat16 h = __float2bfloat16(v);
        g_wh[i] = h;
        g_wl[i] = __float2bfloat16(v - __bfloat162float(h));
    }
    if (i < N_NODES) g_cnt[i] = 0;
}

// split x into bf16 hi/lo
__global__ __launch_bounds__(256) void xsplit_kernel(const float* __restrict__ x, int n4) {
    int i = blockIdx.x * blockDim.x + threadIdx.x;
    if (i >= n4) return;
    float4 v = ((const float4*)x)[i];
    __nv_bfloat16 h0 = __float2bfloat16(v.x), h1 = __float2bfloat16(v.y);
    __nv_bfloat16 h2 = __float2bfloat16(v.z), h3 = __float2bfloat16(v.w);
    __nv_bfloat16 l0 = __float2bfloat16(v.x - __bfloat162float(h0));
    __nv_bfloat16 l1 = __float2bfloat16(v.y - __bfloat162float(h1));
    __nv_bfloat16 l2 = __float2bfloat16(v.z - __bfloat162float(h2));
    __nv_bfloat16 l3 = __float2bfloat16(v.w - __bfloat162float(h3));
    ushort4 hh, ll;
    hh.x = *(unsigned short*)&h0; hh.y = *(unsigned short*)&h1;
    hh.z = *(unsigned short*)&h2; hh.w = *(unsigned short*)&h3;
    ll.x = *(unsigned short*)&l0; ll.y = *(unsigned short*)&l1;
    ll.z = *(unsigned short*)&l2; ll.w = *(unsigned short*)&l3;
    ((ushort4*)g_xhi)[i] = hh;
    ((ushort4*)g_xlo)[i] = ll;
}

// ---------------------------------------------------------------------------
// Tensor-core triple GEMM: C = x @ W[mode], split-bf16 3-pass (hh + hl + lh).
// BM=128, BN=128(=DIM), BK=32, 256 threads = 8 warps (4m x 2n), warp 32x64.
// Epilogue fuses bias / sigmoid per mode. mode0 writes support only.
// ---------------------------------------------------------------------------
#define SA 40
#define SB 136

__global__ __launch_bounds__(256) void gemm3_tc_kernel(
    const float* __restrict__ b2, const float* __restrict__ b3, int M)
{
    __shared__ __nv_bfloat16 Ah[128 * SA], Al[128 * SA];
    __shared__ __nv_bfloat16 Bh[32 * SB],  Bl[32 * SB];

    const int mode = blockIdx.y;
    const int m0   = blockIdx.x * 128;
    const int tid  = threadIdx.x;
    const int warp = tid >> 5;
    const int lane = tid & 31;
    const int wm   = warp & 3;       // 4 warps along M (32 rows each)
    const int wn   = warp >> 2;      // 2 warps along N (64 cols each)

    const size_t wbase = (size_t)mode * DIM * DIM;

    float acc[2][8][4];
#pragma unroll
    for (int a = 0; a < 2; a++)
#pragma unroll
        for (int b = 0; b < 8; b++)
#pragma unroll
            for (int c = 0; c < 4; c++) acc[a][b][c] = 0.f;

#pragma unroll
    for (int kb = 0; kb < 4; kb++) {
        const int k0 = kb * 32;
        // ---- stage A tile (128 x 32) hi/lo ----
#pragma unroll
        for (int l = 0; l < 2; l++) {
            int idx = tid + l * 256;           // 0..511
            int r   = idx >> 2;                // 0..127
            int ch  = (idx & 3) * 8;           // bf16 chunk (16B)
            int gr  = m0 + r;
            uint4 vh = make_uint4(0, 0, 0, 0), vl = make_uint4(0, 0, 0, 0);
            if (gr < M) {
                vh = *(const uint4*)(g_xhi + (size_t)gr * DIM + k0 + ch);
                vl = *(const uint4*)(g_xlo + (size_t)gr * DIM + k0 + ch);
            }
            *(uint4*)(Ah + r * SA + ch) = vh;
            *(uint4*)(Al + r * SA + ch) = vl;
        }
        // ---- stage B tile (32 x 128) hi/lo ----
#pragma unroll
        for (int l = 0; l < 2; l++) {
            int idx = tid + l * 256;
            int r   = idx >> 4;                // 0..31 (k)
            int c   = (idx & 15) * 8;          // 0..120 (n)
            *(uint4*)(Bh + r * SB + c) =
                *(const uint4*)(g_wh + wbase + (size_t)(k0 + r) * DIM + c);
            *(uint4*)(Bl + r * SB + c) =
                *(const uint4*)(g_wl + wbase + (size_t)(k0 + r) * DIM + c);
        }
        __syncthreads();

#pragma unroll
        for (int ks = 0; ks < 2; ks++) {
            // A fragments for the two 16-row tiles of this warp
            uint32_t ah[2][4], al[2][4];
#pragma unroll
            for (int mt = 0; mt < 2; mt++) {
                int rowA = wm * 32 + mt * 16 + (lane & 15);
                int colA = ks * 16 + (lane >> 4) * 8;
                uint32_t ad = smem_u32(Ah + rowA * SA + colA);
                ldsm_x4(ah[mt][0], ah[mt][1], ah[mt][2], ah[mt][3], ad);
                uint32_t ad2 = smem_u32(Al + rowA * SA + colA);
                ldsm_x4(al[mt][0], al[mt][1], al[mt][2], al[mt][3], ad2);
            }
#pragma unroll
            for (int np = 0; np < 4; np++) {   // 16 n-cols per pair
                int rowB = ks * 16 + (lane & 15);
                int colB = wn * 64 + np * 16 + (lane >> 4) * 8;
                uint32_t bh[4], bl[4];
                uint32_t bd = smem_u32(Bh + rowB * SB + colB);
                ldsm_x4_t(bh[0], bh[1], bh[2], bh[3], bd);
                uint32_t bd2 = smem_u32(Bl + rowB * SB + colB);
                ldsm_x4_t(bl[0], bl[1], bl[2], bl[3], bd2);
#pragma unroll
                for (int h = 0; h < 2; h++) {
                    int nt = np * 2 + h;
#pragma unroll
                    for (int mt = 0; mt < 2; mt++) {
                        mma_bf16(acc[mt][nt], ah[mt][0], ah[mt][1], ah[mt][2], ah[mt][3],
                                 bh[h * 2], bh[h * 2 + 1]);
                        mma_bf16(acc[mt][nt], ah[mt][0], ah[mt][1], ah[mt][2], ah[mt][3],
                                 bl[h * 2], bl[h * 2 + 1]);
                        mma_bf16(acc[mt][nt], al[mt][0], al[mt][1], al[mt][2], al[mt][3],
                                 bh[h * 2], bh[h * 2 + 1]);
                    }
                }
            }
        }
        __syncthreads();
    }

    // ---- epilogue: c0,c1 -> (row g, col tg*2..+1); c2,c3 -> row g+8 ----
    const int g  = lane >> 2;
    const int tg = lane & 3;
    float* dst = (mode == 0) ? g_support : ((mode == 1) ? g_trans : g_gate);
#pragma unroll
    for (int mt = 0; mt < 2; mt++) {
#pragma unroll
        for (int nt = 0; nt < 8; nt++) {
            int col  = wn * 64 + nt * 8 + tg * 2;
            int row0 = m0 + wm * 32 + mt * 16 + g;
            int row1 = row0 + 8;
            float v0 = acc[mt][nt][0], v1 = acc[mt][nt][1];
            float v2 = acc[mt][nt][2], v3 = acc[mt][nt][3];
            if (mode == 1) {
                float2 bb = *(const float2*)(b2 + col);
                v0 += bb.x; v1 += bb.y; v2 += bb.x; v3 += bb.y;
            } else if (mode == 2) {
                float2 bb = *(const float2*)(b3 + col);
                v0 = 1.f / (1.f + __expf(-(v0 + bb.x)));
                v1 = 1.f / (1.f + __expf(-(v1 + bb.y)));
                v2 = 1.f / (1.f + __expf(-(v2 + bb.x)));
                v3 = 1.f / (1.f + __expf(-(v3 + bb.y)));
            }
            if (row0 < M) *(float2*)(dst + (size_t)row0 * DIM + col) = make_float2(v0, v1);
            if (row1 < M) *(float2*)(dst + (size_t)row1 * DIM + col) = make_float2(v2, v3);
        }
    }
}

// ---------------------------------------------------------------------------
// CSR build: histogram -> single-block scan -> fill
// ---------------------------------------------------------------------------
__global__ __launch_bounds__(256) void hist_kernel(const int* __restrict__ edst, int E) {
    int i = blockIdx.x * blockDim.x + threadIdx.x;
    if (i < E) atomicAdd(&g_cnt[edst[i]], 1);
}

__global__ __launch_bounds__(1024) void scan_kernel(int E) {
    __shared__ int sp[1024];
    const int t = threadIdx.x;
    const int chunk = (N_NODES + 1023) / 1024;
    const int base  = t * chunk;
    int mysum = 0;
    for (int i = 0; i < chunk; i++) {
        int n = base + i;
        if (n < N_NODES) mysum += g_cnt[n];
    }
    sp[t] = mysum;
    __syncthreads();
    for (int st = 1; st < 1024; st <<= 1) {
        int v = (t >= st) ? sp[t - st] : 0;
        __syncthreads();
        sp[t] += v;
        __syncthreads();
    }
    int run = sp[t] - mysum;   // exclusive prefix for this thread's chunk
    for (int i = 0; i < chunk; i++) {
        int n = base + i;
        if (n < N_NODES) {
            g_off[n] = run;
            g_cur[n] = run;
            run += g_cnt[n];
        }
    }
    if (t == 0) g_off[N_NODES] = E;
}

__global__ __launch_bounds__(256) void fill_kernel(
    const int* __restrict__ esrc, const int* __restrict__ edst,
    const float* __restrict__ ew, int E)
{
    int i = blockIdx.x * blockDim.x + threadIdx.x;
    if (i >= E) return;
    int d = edst[i];
    int p = atomicAdd(&g_cur[d], 1);
    g_csr[p] = make_int2(esrc[i], __float_as_int(ew[i]));
}

// ---------------------------------------------------------------------------
// gather + fused final: one warp per dst node, lane owns 4 contiguous cols.
// out = trans + gate * (relu(agg + eps*support + b1) - trans)
// ---------------------------------------------------------------------------
__global__ __launch_bounds__(256) void gather_kernel(
    const float* __restrict__ b1, const float* __restrict__ eps,
    float* __restrict__ out, int M)
{
    int node = (int)((blockIdx.x * blockDim.x + threadIdx.x) >> 5);
    int lane = threadIdx.x & 31;
    if (node >= M) return;

    int start = g_off[node], end = g_off[node + 1];
    float4 acc = make_float4(0.f, 0.f, 0.f, 0.f);

    for (int base = start; base < end; base += 32) {
        int n = min(32, end - base);
        int2 e = (lane < n) ? g_csr[base + lane] : make_int2(0, 0);
        for (int j = 0; j < n; j++) {
            int   s = __shfl_sync(0xffffffffu, e.x, j);
            float w = __int_as_float(__shfl_sync(0xffffffffu, e.y, j));
            float4 v = *((const float4*)(g_support + (size_t)s * DIM) + lane);
            acc.x = fmaf(w, v.x, acc.x);
            acc.y = fmaf(w, v.y, acc.y);
            acc.z = fmaf(w, v.z, acc.z);
            acc.w = fmaf(w, v.w, acc.w);
        }
    }

    const float e = *eps;
    size_t rb = (size_t)node * DIM + lane * 4;
    float4 s  = *(const float4*)(g_support + rb);
    float4 bb = *(const float4*)(b1 + lane * 4);
    float4 a;
    a.x = fmaxf(acc.x + fmaf(e, s.x, bb.x), 0.f);
    a.y = fmaxf(acc.y + fmaf(e, s.y, bb.y), 0.f);
    a.z = fmaxf(acc.z + fmaf(e, s.z, bb.z), 0.f);
    a.w = fmaxf(acc.w + fmaf(e, s.w, bb.w), 0.f);
    float4 t = *(const float4*)(g_trans + rb);
    float4 g = *(const float4*)(g_gate + rb);
    float4 o;
    o.x = t.x + g.x * (a.x - t.x);
    o.y = t.y + g.y * (a.y - t.y);
    o.z = t.z + g.z * (a.z - t.z);
    o.w = t.w + g.w * (a.w - t.w);
    *(float4*)(out + rb) = o;
}

// ---------------------------------------------------------------------------
extern "C" void kernel_launch(void* const* d_in, const int* in_sizes, int n_in,
                              void* d_out, int out_size)
{
    const float* x    = (const float*)d_in[0];
    const int*   esrc = (const int*)d_in[1];
    const int*   edst = (const int*)d_in[2];
    const float* ew   = (const float*)d_in[3];
    const float* w1   = (const float*)d_in[4];
    const float* w2   = (const float*)d_in[5];
    const float* w3   = (const float*)d_in[6];
    const float* b1   = (const float*)d_in[7];
    const float* b2   = (const float*)d_in[8];
    const float* b3   = (const float*)d_in[9];
    const float* eps  = (const float*)d_in[10];

    const int M = in_sizes[0] / DIM;   // 100000
    const int E = in_sizes[1];         // 1600000

    prep_kernel<<<(N_NODES + 255) / 256, 256>>>(w1, w2, w3);

    int n4 = M * DIM / 4;
    xsplit_kernel<<<(n4 + 255) / 256, 256>>>(x, n4);

    dim3 gg((M + 127) / 128, 3);
    gemm3_tc_kernel<<<gg, 256>>>(b2, b3, M);

    hist_kernel<<<(E + 255) / 256, 256>>>(edst, E);
    scan_kernel<<<1, 1024>>>(E);
    fill_kernel<<<(E + 255) / 256, 256>>>(esrc, edst, ew, E);

    int gthreads = M * 32;
    gather_kernel<<<(gthreads + 255) / 256, 256>>>(b1, eps, (float*)d_out, M);
}

// round 5
// speedup vs baseline: 1.8433x; 1.5939x over previous
#include <cuda_runtime.h>
#include <cuda_bf16.h>
#include <cstdint>

#define N_NODES 100000
#define N_EDGES_MAX 1600000
#define DIM 128

// ---------------- scratch (allocation-free rule: __device__ globals) -------
__device__ float g_support[(size_t)N_NODES * DIM];
__device__ float g_trans[(size_t)N_NODES * DIM];
__device__ float g_gate[(size_t)N_NODES * DIM];

__device__ int  g_cnt[N_NODES];
__device__ int  g_off[N_NODES + 1];
__device__ int  g_cur[N_NODES];
__device__ int2 g_csr[N_EDGES_MAX];   // {src, float_bits(weight)} bucketed by dst
__device__ int  g_bsum[1024];
__device__ int  g_ebsum[1024];

// ---------------------------------------------------------------------------
// helpers
// ---------------------------------------------------------------------------
__device__ __forceinline__ uint32_t smem_u32(const void* p) {
    return (uint32_t)__cvta_generic_to_shared(p);
}
__device__ __forceinline__ void ldsm_x4(uint32_t& r0, uint32_t& r1, uint32_t& r2,
                                        uint32_t& r3, uint32_t addr) {
    asm volatile("ldmatrix.sync.aligned.m8n8.x4.shared.b16 {%0,%1,%2,%3}, [%4];"
                 : "=r"(r0), "=r"(r1), "=r"(r2), "=r"(r3) : "r"(addr));
}
__device__ __forceinline__ void ldsm_x4_t(uint32_t& r0, uint32_t& r1, uint32_t& r2,
                                          uint32_t& r3, uint32_t addr) {
    asm volatile("ldmatrix.sync.aligned.m8n8.x4.trans.shared.b16 {%0,%1,%2,%3}, [%4];"
                 : "=r"(r0), "=r"(r1), "=r"(r2), "=r"(r3) : "r"(addr));
}
__device__ __forceinline__ void mma_bf16(float* c, uint32_t a0, uint32_t a1,
                                         uint32_t a2, uint32_t a3,
                                         uint32_t b0, uint32_t b1) {
    asm volatile(
        "mma.sync.aligned.m16n8k16.row.col.f32.bf16.bf16.f32 "
        "{%0,%1,%2,%3}, {%4,%5,%6,%7}, {%8,%9}, {%0,%1,%2,%3};"
        : "+f"(c[0]), "+f"(c[1]), "+f"(c[2]), "+f"(c[3])
        : "r"(a0), "r"(a1), "r"(a2), "r"(a3), "r"(b0), "r"(b1));
}

__device__ __forceinline__ void split4(float4 v, ushort4& hh, ushort4& ll) {
    __nv_bfloat16 h0 = __float2bfloat16(v.x), h1 = __float2bfloat16(v.y);
    __nv_bfloat16 h2 = __float2bfloat16(v.z), h3 = __float2bfloat16(v.w);
    __nv_bfloat16 l0 = __float2bfloat16(v.x - __bfloat162float(h0));
    __nv_bfloat16 l1 = __float2bfloat16(v.y - __bfloat162float(h1));
    __nv_bfloat16 l2 = __float2bfloat16(v.z - __bfloat162float(h2));
    __nv_bfloat16 l3 = __float2bfloat16(v.w - __bfloat162float(h3));
    hh.x = *(unsigned short*)&h0; hh.y = *(unsigned short*)&h1;
    hh.z = *(unsigned short*)&h2; hh.w = *(unsigned short*)&h3;
    ll.x = *(unsigned short*)&l0; ll.y = *(unsigned short*)&l1;
    ll.z = *(unsigned short*)&l2; ll.w = *(unsigned short*)&l3;
}

// ---------------------------------------------------------------------------
__global__ __launch_bounds__(256) void zero_kernel(int M) {
    int i = blockIdx.x * blockDim.x + threadIdx.x;
    if (i < M) g_cnt[i] = 0;
}

// ---------------------------------------------------------------------------
// dst-degree histogram (standalone, as in the round-2 kernel that ran fine)
// ---------------------------------------------------------------------------
__global__ __launch_bounds__(256) void hist_kernel(const int* __restrict__ edst, int E) {
    int i = blockIdx.x * blockDim.x + threadIdx.x;
    if (i < E) atomicAdd(&g_cnt[edst[i]], 1);
}

// ---------------------------------------------------------------------------
// Tensor-core triple GEMM: C = x @ W[mode], split-bf16 3-pass (hh + hl + lh).
// In-kernel fp32->bf16 hi/lo split while staging shared memory.
// BM=128, BN=128(=DIM), BK=32, 256 threads = 8 warps (4m x 2n).
// grid.x = row tiles, grid.y = mode (0:support, 1:trans+b2, 2:sigmoid(gate+b3))
// ---------------------------------------------------------------------------
#define SA 40
#define SB 136

__global__ __launch_bounds__(256) void gemm3_tc_kernel(
    const float* __restrict__ x,
    const float* __restrict__ w1, const float* __restrict__ w2,
    const float* __restrict__ w3,
    const float* __restrict__ b2, const float* __restrict__ b3, int M)
{
    __shared__ __nv_bfloat16 Ah[128 * SA], Al[128 * SA];
    __shared__ __nv_bfloat16 Bh[32 * SB],  Bl[32 * SB];

    const int tid  = threadIdx.x;
    const int mode = blockIdx.y;
    const int m0   = blockIdx.x * 128;
    const int warp = tid >> 5;
    const int lane = tid & 31;
    const int wm   = warp & 3;       // 4 warps along M (32 rows each)
    const int wn   = warp >> 2;      // 2 warps along N (64 cols each)

    const float* __restrict__ W = (mode == 0) ? w1 : ((mode == 1) ? w2 : w3);

    float acc[2][8][4];
#pragma unroll
    for (int a = 0; a < 2; a++)
#pragma unroll
        for (int b = 0; b < 8; b++)
#pragma unroll
            for (int c = 0; c < 4; c++) acc[a][b][c] = 0.f;

#pragma unroll
    for (int kb = 0; kb < 4; kb++) {
        const int k0 = kb * 32;
        // ---- stage A tile (128 rows x 32 k) fp32 -> bf16 hi/lo ----
#pragma unroll
        for (int l = 0; l < 4; l++) {
            int idx = tid + l * 256;            // 0..1023 float4s
            int r   = idx >> 3;                 // 0..127
            int c4  = (idx & 7) * 4;            // 0,4,..,28
            int gr  = m0 + r;
            float4 v = make_float4(0.f, 0.f, 0.f, 0.f);
            if (gr < M) v = *(const float4*)(x + (size_t)gr * DIM + k0 + c4);
            ushort4 hh, ll;
            split4(v, hh, ll);
            *(ushort4*)(Ah + r * SA + c4) = hh;
            *(ushort4*)(Al + r * SA + c4) = ll;
        }
        // ---- stage B tile (32 k x 128 n) fp32 -> bf16 hi/lo ----
#pragma unroll
        for (int l = 0; l < 4; l++) {
            int idx = tid + l * 256;
            int r   = idx >> 5;                 // 0..31 (k)
            int c4  = (idx & 31) * 4;           // 0..124 (n)
            float4 v = *(const float4*)(W + (size_t)(k0 + r) * DIM + c4);
            ushort4 hh, ll;
            split4(v, hh, ll);
            *(ushort4*)(Bh + r * SB + c4) = hh;
            *(ushort4*)(Bl + r * SB + c4) = ll;
        }
        __syncthreads();

#pragma unroll
        for (int ks = 0; ks < 2; ks++) {
            uint32_t ah[2][4], al[2][4];
#pragma unroll
            for (int mt = 0; mt < 2; mt++) {
                int rowA = wm * 32 + mt * 16 + (lane & 15);
                int colA = ks * 16 + (lane >> 4) * 8;
                ldsm_x4(ah[mt][0], ah[mt][1], ah[mt][2], ah[mt][3],
                        smem_u32(Ah + rowA * SA + colA));
                ldsm_x4(al[mt][0], al[mt][1], al[mt][2], al[mt][3],
                        smem_u32(Al + rowA * SA + colA));
            }
#pragma unroll
            for (int np = 0; np < 4; np++) {   // 16 n-cols per pair
                int rowB = ks * 16 + (lane & 15);
                int colB = wn * 64 + np * 16 + (lane >> 4) * 8;
                uint32_t bh[4], bl[4];
                ldsm_x4_t(bh[0], bh[1], bh[2], bh[3], smem_u32(Bh + rowB * SB + colB));
                ldsm_x4_t(bl[0], bl[1], bl[2], bl[3], smem_u32(Bl + rowB * SB + colB));
#pragma unroll
                for (int h = 0; h < 2; h++) {
                    int nt = np * 2 + h;
#pragma unroll
                    for (int mt = 0; mt < 2; mt++) {
                        mma_bf16(acc[mt][nt], ah[mt][0], ah[mt][1], ah[mt][2], ah[mt][3],
                                 bh[h * 2], bh[h * 2 + 1]);
                        mma_bf16(acc[mt][nt], ah[mt][0], ah[mt][1], ah[mt][2], ah[mt][3],
                                 bl[h * 2], bl[h * 2 + 1]);
                        mma_bf16(acc[mt][nt], al[mt][0], al[mt][1], al[mt][2], al[mt][3],
                                 bh[h * 2], bh[h * 2 + 1]);
                    }
                }
            }
        }
        __syncthreads();
    }

    // ---- epilogue ----
    const int g  = lane >> 2;
    const int tg = lane & 3;
    float* dst = (mode == 0) ? g_support : ((mode == 1) ? g_trans : g_gate);
#pragma unroll
    for (int mt = 0; mt < 2; mt++) {
#pragma unroll
        for (int nt = 0; nt < 8; nt++) {
            int col  = wn * 64 + nt * 8 + tg * 2;
            int row0 = m0 + wm * 32 + mt * 16 + g;
            int row1 = row0 + 8;
            float v0 = acc[mt][nt][0], v1 = acc[mt][nt][1];
            float v2 = acc[mt][nt][2], v3 = acc[mt][nt][3];
            if (mode == 1) {
                float2 bb = *(const float2*)(b2 + col);
                v0 += bb.x; v1 += bb.y; v2 += bb.x; v3 += bb.y;
            } else if (mode == 2) {
                float2 bb = *(const float2*)(b3 + col);
                v0 = 1.f / (1.f + __expf(-(v0 + bb.x)));
                v1 = 1.f / (1.f + __expf(-(v1 + bb.y)));
                v2 = 1.f / (1.f + __expf(-(v2 + bb.x)));
                v3 = 1.f / (1.f + __expf(-(v3 + bb.y)));
            }
            if (row0 < M) *(float2*)(dst + (size_t)row0 * DIM + col) = make_float2(v0, v1);
            if (row1 < M) *(float2*)(dst + (size_t)row1 * DIM + col) = make_float2(v2, v3);
        }
    }
}

// ---------------------------------------------------------------------------
// Coalesced 3-phase exclusive scan of g_cnt -> g_off / g_cur
// ---------------------------------------------------------------------------
__global__ __launch_bounds__(256) void scan_p1(int M) {
    __shared__ int sp[256];
    int i = blockIdx.x * 256 + threadIdx.x;
    int v = (i < M) ? g_cnt[i] : 0;
    sp[threadIdx.x] = v;
    __syncthreads();
#pragma unroll
    for (int st = 128; st > 0; st >>= 1) {
        if (threadIdx.x < st) sp[threadIdx.x] += sp[threadIdx.x + st];
        __syncthreads();
    }
    if (threadIdx.x == 0) g_bsum[blockIdx.x] = sp[0];
}

__global__ __launch_bounds__(512) void scan_p2(int NB, int E, int M) {
    __shared__ int sp[512];
    int t = threadIdx.x;
    int v = (t < NB) ? g_bsum[t] : 0;
    sp[t] = v;
    __syncthreads();
#pragma unroll
    for (int st = 1; st < 512; st <<= 1) {
        int u = (t >= st) ? sp[t - st] : 0;
        __syncthreads();
        sp[t] += u;
        __syncthreads();
    }
    if (t < NB) g_ebsum[t] = sp[t] - v;     // exclusive
    if (t == 0) g_off[M] = E;
}

__global__ __launch_bounds__(256) void scan_p3(int M) {
    __shared__ int sp[256];
    int t = threadIdx.x;
    int i = blockIdx.x * 256 + t;
    int v = (i < M) ? g_cnt[i] : 0;
    sp[t] = v;
    __syncthreads();
#pragma unroll
    for (int st = 1; st < 256; st <<= 1) {
        int u = (t >= st) ? sp[t - st] : 0;
        __syncthreads();
        sp[t] += u;
        __syncthreads();
    }
    if (i < M) {
        int off = g_ebsum[blockIdx.x] + sp[t] - v;
        g_off[i] = off;
        g_cur[i] = off;
    }
}

// ---------------------------------------------------------------------------
__global__ __launch_bounds__(256) void fill_kernel(
    const int* __restrict__ esrc, const int* __restrict__ edst,
    const float* __restrict__ ew, int E)
{
    int i = blockIdx.x * blockDim.x + threadIdx.x;
    if (i >= E) return;
    int d = edst[i];
    int p = atomicAdd(&g_cur[d], 1);
    g_csr[p] = make_int2(esrc[i], __float_as_int(ew[i]));
}

// ---------------------------------------------------------------------------
// gather + fused final: one warp per dst node, lane owns 4 contiguous cols.
// out = trans + gate * (relu(agg + eps*support + b1) - trans)
// ---------------------------------------------------------------------------
__global__ __launch_bounds__(256) void gather_kernel(
    const float* __restrict__ b1, const float* __restrict__ eps,
    float* __restrict__ out, int M)
{
    int node = (int)((blockIdx.x * blockDim.x + threadIdx.x) >> 5);
    int lane = threadIdx.x & 31;
    if (node >= M) return;

    int start = g_off[node], end = g_off[node + 1];
    float4 acc0 = make_float4(0.f, 0.f, 0.f, 0.f);
    float4 acc1 = make_float4(0.f, 0.f, 0.f, 0.f);

    int j = start;
    for (; j + 2 <= end; j += 2) {
        int2  e0 = *(const int2*)(g_csr + j);       // uniform: L1 broadcast
        int2  e1 = *(const int2*)(g_csr + j + 1);
        float w0 = __int_as_float(e0.y);
        float w1 = __int_as_float(e1.y);
        float4 v0 = *((const float4*)(g_support + (size_t)e0.x * DIM) + lane);
        float4 v1 = *((const float4*)(g_support + (size_t)e1.x * DIM) + lane);
        acc0.x = fmaf(w0, v0.x, acc0.x);
        acc0.y = fmaf(w0, v0.y, acc0.y);
        acc0.z = fmaf(w0, v0.z, acc0.z);
        acc0.w = fmaf(w0, v0.w, acc0.w);
        acc1.x = fmaf(w1, v1.x, acc1.x);
        acc1.y = fmaf(w1, v1.y, acc1.y);
        acc1.z = fmaf(w1, v1.z, acc1.z);
        acc1.w = fmaf(w1, v1.w, acc1.w);
    }
    if (j < end) {
        int2  e = *(const int2*)(g_csr + j);
        float w = __int_as_float(e.y);
        float4 v = *((const float4*)(g_support + (size_t)e.x * DIM) + lane);
        acc0.x = fmaf(w, v.x, acc0.x);
        acc0.y = fmaf(w, v.y, acc0.y);
        acc0.z = fmaf(w, v.z, acc0.z);
        acc0.w = fmaf(w, v.w, acc0.w);
    }
    acc0.x += acc1.x; acc0.y += acc1.y; acc0.z += acc1.z; acc0.w += acc1.w;

    const float e = *eps;
    size_t rb = (size_t)node * DIM + lane * 4;
    float4 s  = *(const float4*)(g_support + rb);
    float4 bb = *(const float4*)(b1 + lane * 4);
    float4 a;
    a.x = fmaxf(acc0.x + fmaf(e, s.x, bb.x), 0.f);
    a.y = fmaxf(acc0.y + fmaf(e, s.y, bb.y), 0.f);
    a.z = fmaxf(acc0.z + fmaf(e, s.z, bb.z), 0.f);
    a.w = fmaxf(acc0.w + fmaf(e, s.w, bb.w), 0.f);
    float4 t = *(const float4*)(g_trans + rb);
    float4 g = *(const float4*)(g_gate + rb);
    float4 o;
    o.x = t.x + g.x * (a.x - t.x);
    o.y = t.y + g.y * (a.y - t.y);
    o.z = t.z + g.z * (a.z - t.z);
    o.w = t.w + g.w * (a.w - t.w);
    *(float4*)(out + rb) = o;
}

// ---------------------------------------------------------------------------
extern "C" void kernel_launch(void* const* d_in, const int* in_sizes, int n_in,
                              void* d_out, int out_size)
{
    const float* x    = (const float*)d_in[0];
    const int*   esrc = (const int*)d_in[1];
    const int*   edst = (const int*)d_in[2];
    const float* ew   = (const float*)d_in[3];
    const float* w1   = (const float*)d_in[4];
    const float* w2   = (const float*)d_in[5];
    const float* w3   = (const float*)d_in[6];
    const float* b1   = (const float*)d_in[7];
    const float* b2   = (const float*)d_in[8];
    const float* b3   = (const float*)d_in[9];
    const float* eps  = (const float*)d_in[10];

    const int M = in_sizes[0] / DIM;   // 100000
    const int E = in_sizes[1];         // 1600000
    const int NB = (M + 255) / 256;    // 391

    zero_kernel<<<NB, 256>>>(M);
    hist_kernel<<<(E + 255) / 256, 256>>>(edst, E);

    dim3 gg((M + 127) / 128, 3);
    gemm3_tc_kernel<<<gg, 256>>>(x, w1, w2, w3, b2, b3, M);

    scan_p1<<<NB, 256>>>(M);
    scan_p2<<<1, 512>>>(NB, E, M);
    scan_p3<<<NB, 256>>>(M);

    fill_kernel<<<(E + 255) / 256, 256>>>(esrc, edst, ew, E);

    int gthreads = M * 32;
    gather_kernel<<<(gthreads + 255) / 256, 256>>>(b1, eps, (float*)d_out, M);
}